// round 5
// baseline (speedup 1.0000x reference)
#include <cuda_runtime.h>
#include <cuda_bf16.h>
#include <cuda_fp16.h>
#include <cstdint>

#define N_TOK 1024
#define DH    64
#define NB    8
#define NGH   4
#define NLH   8
#define NLVL  4
#define NN    (N_TOK * N_TOK)
#define NBG   (NB * NGH)          // 32
#define KSTEPS 12
#define SROW   136

typedef unsigned long long u64t;

// ---------------- scratch ----------------
__device__ __half g_S[(size_t)NBG * NN];                      // 64 MB

__device__ __forceinline__ uint32_t smem_u32(const void* p) {
    uint32_t a;
    asm("{ .reg .u64 t; cvta.to.shared.u64 t, %1; cvt.u32.u64 %0, t; }" : "=r"(a) : "l"(p));
    return a;
}

// ---------------- packed f32x2 helpers ----------------
__device__ __forceinline__ u64t pack2(float a, float b) {
    u64t r; asm("mov.b64 %0, {%1, %2};" : "=l"(r) : "f"(a), "f"(b)); return r;
}
__device__ __forceinline__ void unpack2(u64t p, float& a, float& b) {
    asm("mov.b64 {%0, %1}, %2;" : "=f"(a), "=f"(b) : "l"(p));
}
__device__ __forceinline__ u64t mul2(u64t a, u64t b) {
    u64t d; asm("mul.rn.f32x2 %0, %1, %2;" : "=l"(d) : "l"(a), "l"(b)); return d;
}
__device__ __forceinline__ u64t fma2(u64t a, u64t b, u64t c) {
    u64t d; asm("fma.rn.f32x2 %0, %1, %2, %3;" : "=l"(d) : "l"(a), "l"(b), "l"(c)); return d;
}

// ---------------------------------------------------------------------------
// Kernel 1: fused split + mma.sync bf16 GEMM (3-term bf16 split, K=192 eff.)
// ---------------------------------------------------------------------------
#define SM_BYTES (2 * 128 * SROW * 2)    // 69632

__global__ __launch_bounds__(256)
void qk_gemm_mma(const float* __restrict__ q, const float* __restrict__ k)
{
    extern __shared__ __align__(16) char smem[];
    __nv_bfloat16* As = (__nv_bfloat16*)smem;          // [128][SROW]
    __nv_bfloat16* Bs = As + 128 * SROW;

    const int tid  = threadIdx.x;
    const int lane = tid & 31;
    const int w    = tid >> 5;
    const int wm   = (w & 1) * 64;
    const int wn   = (w >> 1) * 32;

    const int bg = blockIdx.z;
    const int qt = blockIdx.y * 128;
    const int kt = blockIdx.x * 128;

    const float* Qg = q + ((size_t)bg * N_TOK + qt) * DH;
    const float* Kg = k + ((size_t)bg * N_TOK + kt) * DH;

#pragma unroll
    for (int it = 0; it < 8; it++) {
        int idx = it * 256 + tid;
        int row = idx >> 4;
        int c4  = (idx & 15) * 4;
        float4 qv = *(const float4*)(Qg + (size_t)row * DH + c4);
        float4 kv = *(const float4*)(Kg + (size_t)row * DH + c4);

        __nv_bfloat16 qh0 = __float2bfloat16(qv.x), qh1 = __float2bfloat16(qv.y);
        __nv_bfloat16 qh2 = __float2bfloat16(qv.z), qh3 = __float2bfloat16(qv.w);
        __nv_bfloat16 ql0 = __float2bfloat16(qv.x - __bfloat162float(qh0));
        __nv_bfloat16 ql1 = __float2bfloat16(qv.y - __bfloat162float(qh1));
        __nv_bfloat16 ql2 = __float2bfloat16(qv.z - __bfloat162float(qh2));
        __nv_bfloat16 ql3 = __float2bfloat16(qv.w - __bfloat162float(qh3));
        __nv_bfloat16 kh0 = __float2bfloat16(kv.x), kh1 = __float2bfloat16(kv.y);
        __nv_bfloat16 kh2 = __float2bfloat16(kv.z), kh3 = __float2bfloat16(kv.w);
        __nv_bfloat16 kl0 = __float2bfloat16(kv.x - __bfloat162float(kh0));
        __nv_bfloat16 kl1 = __float2bfloat16(kv.y - __bfloat162float(kh1));
        __nv_bfloat16 kl2 = __float2bfloat16(kv.z - __bfloat162float(kh2));
        __nv_bfloat16 kl3 = __float2bfloat16(kv.w - __bfloat162float(kh3));

        __nv_bfloat16* ap = As + row * SROW + c4;
        __nv_bfloat16* bp = Bs + row * SROW + c4;
        ap[0] = qh0; ap[1] = qh1; ap[2] = qh2; ap[3] = qh3;
        ap[64] = ql0; ap[65] = ql1; ap[66] = ql2; ap[67] = ql3;
        bp[0] = kh0; bp[1] = kh1; bp[2] = kh2; bp[3] = kh3;
        bp[64] = kl0; bp[65] = kl1; bp[66] = kl2; bp[67] = kl3;
    }
    __syncthreads();

    const uint32_t a_base = smem_u32(As);
    const uint32_t b_base = smem_u32(Bs);

    const int arow  = lane & 15;
    const int akoff = (lane >> 4) * 8;
    // B x4: lanes 0-7 -> n rows 0-7 (k lo), 8-15 -> n 0-7 (k hi),
    //       16-23 -> n 8-15 (k lo), 24-31 -> n 8-15 (k hi)
    const int brow  = (lane & 7) + ((lane >> 4) << 3);
    const int bkoff = ((lane >> 3) & 1) * 8;

    float acc[4][4][4];
#pragma unroll
    for (int mi = 0; mi < 4; mi++)
#pragma unroll
        for (int ni = 0; ni < 4; ni++)
#pragma unroll
            for (int r = 0; r < 4; r++) acc[mi][ni][r] = 0.0f;

#pragma unroll
    for (int s = 0; s < KSTEPS; s++) {
        const int ka = (s < 4) ? s * 16 : (s < 8) ? (s - 4) * 16 : 64 + (s - 8) * 16;
        const int kb = (s < 4) ? s * 16 : (s < 8) ? 64 + (s - 4) * 16 : (s - 8) * 16;

        uint32_t af[4][4], bf[4][2];
#pragma unroll
        for (int mi = 0; mi < 4; mi++) {
            uint32_t addr = a_base + (uint32_t)(((wm + mi * 16 + arow) * SROW + ka + akoff) * 2);
            asm volatile("ldmatrix.sync.aligned.m8n8.x4.shared.b16 {%0,%1,%2,%3}, [%4];"
                         : "=r"(af[mi][0]), "=r"(af[mi][1]), "=r"(af[mi][2]), "=r"(af[mi][3])
                         : "r"(addr));
        }
#pragma unroll
        for (int nip = 0; nip < 2; nip++) {
            uint32_t addr = b_base + (uint32_t)(((wn + nip * 16 + brow) * SROW + kb + bkoff) * 2);
            asm volatile("ldmatrix.sync.aligned.m8n8.x4.shared.b16 {%0,%1,%2,%3}, [%4];"
                         : "=r"(bf[2 * nip][0]), "=r"(bf[2 * nip][1]),
                           "=r"(bf[2 * nip + 1][0]), "=r"(bf[2 * nip + 1][1])
                         : "r"(addr));
        }
#pragma unroll
        for (int mi = 0; mi < 4; mi++)
#pragma unroll
            for (int ni = 0; ni < 4; ni++) {
                asm volatile(
                    "mma.sync.aligned.m16n8k16.row.col.f32.bf16.bf16.f32 "
                    "{%0,%1,%2,%3}, {%4,%5,%6,%7}, {%8,%9}, {%0,%1,%2,%3};"
                    : "+f"(acc[mi][ni][0]), "+f"(acc[mi][ni][1]),
                      "+f"(acc[mi][ni][2]), "+f"(acc[mi][ni][3])
                    : "r"(af[mi][0]), "r"(af[mi][1]), "r"(af[mi][2]), "r"(af[mi][3]),
                      "r"(bf[ni][0]), "r"(bf[ni][1]));
            }
    }

    __half* __restrict__ Sp = g_S + (size_t)bg * NN;
#pragma unroll
    for (int mi = 0; mi < 4; mi++) {
#pragma unroll
        for (int ni = 0; ni < 4; ni++) {
            int m = qt + wm + mi * 16 + (lane >> 2);
            int n = kt + wn + ni * 8 + (lane & 3) * 2;
            *(__half2*)(Sp + (size_t)m * N_TOK + n) =
                __floats2half2_rn(acc[mi][ni][0], acc[mi][ni][1]);
            *(__half2*)(Sp + (size_t)(m + 8) * N_TOK + n) =
                __floats2half2_rn(acc[mi][ni][2], acc[mi][ni][3]);
        }
    }
}

// ---------------------------------------------------------------------------
// Kernel 2: epilogue with packed f32x2 math (pairs over local-head h).
//   mwp[g*4+hp] = pair {mw[g*8+2hp], mw[g*8+2hp+1]}
//   vp[hp]      = sum_g ps_g * mwp[g*4+hp]        (packed)
//   op[hp]      = sB2[hp] + sum_hh pv[hh] * sWt2[hh*4+hp]
// ---------------------------------------------------------------------------
__global__ __launch_bounds__(256, 4)
void epilogue_kernel(const float* __restrict__ masks,
                     const float* __restrict__ proj,   // [4][32]
                     const float* __restrict__ hw,     // [8][8] (out, in)
                     const float* __restrict__ hb,     // [8]
                     float* __restrict__ out)
{
    __shared__ u64t sP2[64];    // [l][xp]: pair {proj[l*32+2xp], proj[l*32+2xp+1]}
    __shared__ u64t sWt2[32];   // [hh][hp]: pair {W[2hp][hh], W[2hp+1][hh]}
    __shared__ u64t sB2[4];     // pair {hb[2hp], hb[2hp+1]}

    const int tid = threadIdx.x;
    if (tid < 64) {
        int l = tid >> 4, xp = tid & 15;
        sP2[tid] = pack2(proj[l * 32 + 2 * xp], proj[l * 32 + 2 * xp + 1]);
    }
    if (tid < 32) {
        int hh = tid >> 2, hp = tid & 3;
        sWt2[tid] = pack2(hw[(2 * hp) * 8 + hh], hw[(2 * hp + 1) * 8 + hh]);
    }
    if (tid < 4) sB2[tid] = pack2(hb[2 * tid], hb[2 * tid + 1]);
    __syncthreads();

    const size_t i = (size_t)blockIdx.x * 256 + tid;
    float4 m = *(const float4*)(masks + 4 * i);
    u64t mx = pack2(m.x, m.x), my = pack2(m.y, m.y);
    u64t mz = pack2(m.z, m.z), mq = pack2(m.w, m.w);

    u64t mwp[16];
#pragma unroll
    for (int xp = 0; xp < 16; xp++) {
        u64t t = mul2(mx, sP2[xp]);
        t = fma2(my, sP2[16 + xp], t);
        t = fma2(mz, sP2[32 + xp], t);
        t = fma2(mq, sP2[48 + xp], t);
        mwp[xp] = t;
    }

    const __half* __restrict__ Sp = g_S + i;

    // software-pipelined S loads across the b-loop
    float s0 = __half2float(Sp[(size_t)0 << 20]);
    float s1 = __half2float(Sp[(size_t)1 << 20]);
    float s2 = __half2float(Sp[(size_t)2 << 20]);
    float s3 = __half2float(Sp[(size_t)3 << 20]);

#pragma unroll
    for (int b = 0; b < NB; b++) {
        float n0, n1, n2, n3;
        if (b < NB - 1) {
            n0 = __half2float(Sp[((size_t)(b * 4 + 4)) << 20]);
            n1 = __half2float(Sp[((size_t)(b * 4 + 5)) << 20]);
            n2 = __half2float(Sp[((size_t)(b * 4 + 6)) << 20]);
            n3 = __half2float(Sp[((size_t)(b * 4 + 7)) << 20]);
        }

        u64t ps0 = pack2(s0, s0), ps1 = pack2(s1, s1);
        u64t ps2 = pack2(s2, s2), ps3 = pack2(s3, s3);

        // mix over g (packed over h-pairs), then relu + broadcast packs
        u64t pv[8];
#pragma unroll
        for (int hp = 0; hp < 4; hp++) {
            u64t t = mul2(ps0, mwp[hp]);
            t = fma2(ps1, mwp[4 + hp], t);
            t = fma2(ps2, mwp[8 + hp], t);
            t = fma2(ps3, mwp[12 + hp], t);
            float v0, v1; unpack2(t, v0, v1);
            v0 = fmaxf(v0, 0.0f); v1 = fmaxf(v1, 0.0f);
            pv[2 * hp]     = pack2(v0, v0);
            pv[2 * hp + 1] = pack2(v1, v1);
        }

        // head projection (packed over h-pairs) + store
#pragma unroll
        for (int hp = 0; hp < 4; hp++) {
            u64t o = sB2[hp];
#pragma unroll
            for (int hh = 0; hh < 8; hh++)
                o = fma2(pv[hh], sWt2[hh * 4 + hp], o);
            float o0, o1; unpack2(o, o0, o1);
            out[((size_t)(b * 8 + 2 * hp)     << 20) + i] = o0;
            out[((size_t)(b * 8 + 2 * hp + 1) << 20) + i] = o1;
        }

        s0 = n0; s1 = n1; s2 = n2; s3 = n3;
    }
}

extern "C" void kernel_launch(void* const* d_in, const int* in_sizes, int n_in,
                              void* d_out, int out_size)
{
    const float* q     = (const float*)d_in[0];
    const float* k     = (const float*)d_in[1];
    const float* masks = (const float*)d_in[2];
    const float* proj  = (const float*)d_in[3];
    const float* hw    = (const float*)d_in[4];
    const float* hb    = (const float*)d_in[5];
    float* out = (float*)d_out;

    cudaFuncSetAttribute(qk_gemm_mma, cudaFuncAttributeMaxDynamicSharedMemorySize, SM_BYTES);

    dim3 g1(N_TOK / 128, N_TOK / 128, NBG);
    qk_gemm_mma<<<g1, 256, SM_BYTES>>>(q, k);

    epilogue_kernel<<<NN / 256, 256>>>(masks, proj, hw, hb, out);
}

// round 6
// speedup vs baseline: 1.0203x; 1.0203x over previous
#include <cuda_runtime.h>
#include <cuda_bf16.h>
#include <cuda_fp16.h>
#include <cstdint>

#define N_TOK 1024
#define DH    64
#define NB    8
#define NGH   4
#define NLH   8
#define NLVL  4
#define NN    (N_TOK * N_TOK)
#define NBG   (NB * NGH)          // 32
#define KSTEPS 12
#define SROW   136

typedef unsigned long long u64t;

// ---------------- scratch ----------------
__device__ __half g_S[(size_t)NBG * NN];                      // 64 MB

__device__ __forceinline__ uint32_t smem_u32(const void* p) {
    uint32_t a;
    asm("{ .reg .u64 t; cvta.to.shared.u64 t, %1; cvt.u32.u64 %0, t; }" : "=r"(a) : "l"(p));
    return a;
}

// ---------------- packed f32x2 helpers ----------------
__device__ __forceinline__ u64t pack2(float a, float b) {
    u64t r; asm("mov.b64 %0, {%1, %2};" : "=l"(r) : "f"(a), "f"(b)); return r;
}
__device__ __forceinline__ void unpack2(u64t p, float& a, float& b) {
    asm("mov.b64 {%0, %1}, %2;" : "=f"(a), "=f"(b) : "l"(p));
}
__device__ __forceinline__ u64t mul2(u64t a, u64t b) {
    u64t d; asm("mul.rn.f32x2 %0, %1, %2;" : "=l"(d) : "l"(a), "l"(b)); return d;
}
__device__ __forceinline__ u64t fma2(u64t a, u64t b, u64t c) {
    u64t d; asm("fma.rn.f32x2 %0, %1, %2, %3;" : "=l"(d) : "l"(a), "l"(b), "l"(c)); return d;
}

// ---------------------------------------------------------------------------
// Kernel 1: fused split + mma.sync bf16 GEMM (3-term bf16 split, K=192 eff.)
// ---------------------------------------------------------------------------
#define SM_BYTES (2 * 128 * SROW * 2)    // 69632

__global__ __launch_bounds__(256)
void qk_gemm_mma(const float* __restrict__ q, const float* __restrict__ k)
{
    extern __shared__ __align__(16) char smem[];
    __nv_bfloat16* As = (__nv_bfloat16*)smem;          // [128][SROW]
    __nv_bfloat16* Bs = As + 128 * SROW;

    const int tid  = threadIdx.x;
    const int lane = tid & 31;
    const int w    = tid >> 5;
    const int wm   = (w & 1) * 64;
    const int wn   = (w >> 1) * 32;

    const int bg = blockIdx.z;
    const int qt = blockIdx.y * 128;
    const int kt = blockIdx.x * 128;

    const float* Qg = q + ((size_t)bg * N_TOK + qt) * DH;
    const float* Kg = k + ((size_t)bg * N_TOK + kt) * DH;

#pragma unroll
    for (int it = 0; it < 8; it++) {
        int idx = it * 256 + tid;
        int row = idx >> 4;
        int c4  = (idx & 15) * 4;
        float4 qv = *(const float4*)(Qg + (size_t)row * DH + c4);
        float4 kv = *(const float4*)(Kg + (size_t)row * DH + c4);

        __nv_bfloat16 qh0 = __float2bfloat16(qv.x), qh1 = __float2bfloat16(qv.y);
        __nv_bfloat16 qh2 = __float2bfloat16(qv.z), qh3 = __float2bfloat16(qv.w);
        __nv_bfloat16 ql0 = __float2bfloat16(qv.x - __bfloat162float(qh0));
        __nv_bfloat16 ql1 = __float2bfloat16(qv.y - __bfloat162float(qh1));
        __nv_bfloat16 ql2 = __float2bfloat16(qv.z - __bfloat162float(qh2));
        __nv_bfloat16 ql3 = __float2bfloat16(qv.w - __bfloat162float(qh3));
        __nv_bfloat16 kh0 = __float2bfloat16(kv.x), kh1 = __float2bfloat16(kv.y);
        __nv_bfloat16 kh2 = __float2bfloat16(kv.z), kh3 = __float2bfloat16(kv.w);
        __nv_bfloat16 kl0 = __float2bfloat16(kv.x - __bfloat162float(kh0));
        __nv_bfloat16 kl1 = __float2bfloat16(kv.y - __bfloat162float(kh1));
        __nv_bfloat16 kl2 = __float2bfloat16(kv.z - __bfloat162float(kh2));
        __nv_bfloat16 kl3 = __float2bfloat16(kv.w - __bfloat162float(kh3));

        __nv_bfloat16* ap = As + row * SROW + c4;
        __nv_bfloat16* bp = Bs + row * SROW + c4;
        ap[0] = qh0; ap[1] = qh1; ap[2] = qh2; ap[3] = qh3;
        ap[64] = ql0; ap[65] = ql1; ap[66] = ql2; ap[67] = ql3;
        bp[0] = kh0; bp[1] = kh1; bp[2] = kh2; bp[3] = kh3;
        bp[64] = kl0; bp[65] = kl1; bp[66] = kl2; bp[67] = kl3;
    }
    __syncthreads();

    const uint32_t a_base = smem_u32(As);
    const uint32_t b_base = smem_u32(Bs);

    const int arow  = lane & 15;
    const int akoff = (lane >> 4) * 8;
    const int brow  = (lane & 7) + ((lane >> 4) << 3);
    const int bkoff = ((lane >> 3) & 1) * 8;

    float acc[4][4][4];
#pragma unroll
    for (int mi = 0; mi < 4; mi++)
#pragma unroll
        for (int ni = 0; ni < 4; ni++)
#pragma unroll
            for (int r = 0; r < 4; r++) acc[mi][ni][r] = 0.0f;

#pragma unroll
    for (int s = 0; s < KSTEPS; s++) {
        const int ka = (s < 4) ? s * 16 : (s < 8) ? (s - 4) * 16 : 64 + (s - 8) * 16;
        const int kb = (s < 4) ? s * 16 : (s < 8) ? 64 + (s - 4) * 16 : (s - 8) * 16;

        uint32_t af[4][4], bf[4][2];
#pragma unroll
        for (int mi = 0; mi < 4; mi++) {
            uint32_t addr = a_base + (uint32_t)(((wm + mi * 16 + arow) * SROW + ka + akoff) * 2);
            asm volatile("ldmatrix.sync.aligned.m8n8.x4.shared.b16 {%0,%1,%2,%3}, [%4];"
                         : "=r"(af[mi][0]), "=r"(af[mi][1]), "=r"(af[mi][2]), "=r"(af[mi][3])
                         : "r"(addr));
        }
#pragma unroll
        for (int nip = 0; nip < 2; nip++) {
            uint32_t addr = b_base + (uint32_t)(((wn + nip * 16 + brow) * SROW + kb + bkoff) * 2);
            asm volatile("ldmatrix.sync.aligned.m8n8.x4.shared.b16 {%0,%1,%2,%3}, [%4];"
                         : "=r"(bf[2 * nip][0]), "=r"(bf[2 * nip][1]),
                           "=r"(bf[2 * nip + 1][0]), "=r"(bf[2 * nip + 1][1])
                         : "r"(addr));
        }
#pragma unroll
        for (int mi = 0; mi < 4; mi++)
#pragma unroll
            for (int ni = 0; ni < 4; ni++) {
                asm volatile(
                    "mma.sync.aligned.m16n8k16.row.col.f32.bf16.bf16.f32 "
                    "{%0,%1,%2,%3}, {%4,%5,%6,%7}, {%8,%9}, {%0,%1,%2,%3};"
                    : "+f"(acc[mi][ni][0]), "+f"(acc[mi][ni][1]),
                      "+f"(acc[mi][ni][2]), "+f"(acc[mi][ni][3])
                    : "r"(af[mi][0]), "r"(af[mi][1]), "r"(af[mi][2]), "r"(af[mi][3]),
                      "r"(bf[ni][0]), "r"(bf[ni][1]));
            }
    }

    __half* __restrict__ Sp = g_S + (size_t)bg * NN;
#pragma unroll
    for (int mi = 0; mi < 4; mi++) {
#pragma unroll
        for (int ni = 0; ni < 4; ni++) {
            int m = qt + wm + mi * 16 + (lane >> 2);
            int n = kt + wn + ni * 8 + (lane & 3) * 2;
            *(__half2*)(Sp + (size_t)m * N_TOK + n) =
                __floats2half2_rn(acc[mi][ni][0], acc[mi][ni][1]);
            *(__half2*)(Sp + (size_t)(m + 8) * N_TOK + n) =
                __floats2half2_rn(acc[mi][ni][2], acc[mi][ni][3]);
        }
    }
}

// ---------------------------------------------------------------------------
// Kernel 2: epilogue. All 32 S loads issued UP FRONT (independent -> high MLP,
// DRAM-latency hiding), then packed f32x2 math over local-head pairs.
// ---------------------------------------------------------------------------
__global__ __launch_bounds__(256, 3)
void epilogue_kernel(const float* __restrict__ masks,
                     const float* __restrict__ proj,   // [4][32]
                     const float* __restrict__ hw,     // [8][8]
                     const float* __restrict__ hb,     // [8]
                     float* __restrict__ out)
{
    __shared__ u64t sP2[64];
    __shared__ u64t sWt2[32];
    __shared__ u64t sB2[4];

    const int tid = threadIdx.x;
    if (tid < 64) {
        int l = tid >> 4, xp = tid & 15;
        sP2[tid] = pack2(proj[l * 32 + 2 * xp], proj[l * 32 + 2 * xp + 1]);
    }
    if (tid < 32) {
        int hh = tid >> 2, hp = tid & 3;
        sWt2[tid] = pack2(hw[(2 * hp) * 8 + hh], hw[(2 * hp + 1) * 8 + hh]);
    }
    if (tid < 4) sB2[tid] = pack2(hb[2 * tid], hb[2 * tid + 1]);
    __syncthreads();

    const size_t i = (size_t)blockIdx.x * 256 + tid;
    const __half* __restrict__ Sp = g_S + i;

    // ---- issue ALL 32 independent S loads first: maximal MLP ----
    __half sh[NBG];
#pragma unroll
    for (int j = 0; j < NBG; j++) sh[j] = Sp[(size_t)j << 20];

    float4 m = *(const float4*)(masks + 4 * i);
    u64t mx = pack2(m.x, m.x), my = pack2(m.y, m.y);
    u64t mz = pack2(m.z, m.z), mq = pack2(m.w, m.w);

    u64t mwp[16];
#pragma unroll
    for (int xp = 0; xp < 16; xp++) {
        u64t t = mul2(mx, sP2[xp]);
        t = fma2(my, sP2[16 + xp], t);
        t = fma2(mz, sP2[32 + xp], t);
        t = fma2(mq, sP2[48 + xp], t);
        mwp[xp] = t;
    }

#pragma unroll
    for (int b = 0; b < NB; b++) {
        float s0 = __half2float(sh[b * 4 + 0]);
        float s1 = __half2float(sh[b * 4 + 1]);
        float s2 = __half2float(sh[b * 4 + 2]);
        float s3 = __half2float(sh[b * 4 + 3]);

        u64t ps0 = pack2(s0, s0), ps1 = pack2(s1, s1);
        u64t ps2 = pack2(s2, s2), ps3 = pack2(s3, s3);

        u64t pv[8];
#pragma unroll
        for (int hp = 0; hp < 4; hp++) {
            u64t t = mul2(ps0, mwp[hp]);
            t = fma2(ps1, mwp[4 + hp], t);
            t = fma2(ps2, mwp[8 + hp], t);
            t = fma2(ps3, mwp[12 + hp], t);
            float v0, v1; unpack2(t, v0, v1);
            v0 = fmaxf(v0, 0.0f); v1 = fmaxf(v1, 0.0f);
            pv[2 * hp]     = pack2(v0, v0);
            pv[2 * hp + 1] = pack2(v1, v1);
        }

#pragma unroll
        for (int hp = 0; hp < 4; hp++) {
            u64t o = sB2[hp];
#pragma unroll
            for (int hh = 0; hh < 8; hh++)
                o = fma2(pv[hh], sWt2[hh * 4 + hp], o);
            float o0, o1; unpack2(o, o0, o1);
            out[((size_t)(b * 8 + 2 * hp)     << 20) + i] = o0;
            out[((size_t)(b * 8 + 2 * hp + 1) << 20) + i] = o1;
        }
    }
}

extern "C" void kernel_launch(void* const* d_in, const int* in_sizes, int n_in,
                              void* d_out, int out_size)
{
    const float* q     = (const float*)d_in[0];
    const float* k     = (const float*)d_in[1];
    const float* masks = (const float*)d_in[2];
    const float* proj  = (const float*)d_in[3];
    const float* hw    = (const float*)d_in[4];
    const float* hb    = (const float*)d_in[5];
    float* out = (float*)d_out;

    cudaFuncSetAttribute(qk_gemm_mma, cudaFuncAttributeMaxDynamicSharedMemorySize, SM_BYTES);

    dim3 g1(N_TOK / 128, N_TOK / 128, NBG);
    qk_gemm_mma<<<g1, 256, SM_BYTES>>>(q, k);

    epilogue_kernel<<<NN / 256, 256>>>(masks, proj, hw, hb, out);
}

// round 7
// speedup vs baseline: 1.1411x; 1.1184x over previous
#include <cuda_runtime.h>
#include <cuda_bf16.h>
#include <cuda_fp16.h>
#include <cstdint>

#define N_TOK 1024
#define DH    64
#define NB    8
#define NGH   4
#define NLH   8
#define NLVL  4
#define NN    (N_TOK * N_TOK)
#define NBG   (NB * NGH)          // 32
#define KSTEPS 12
#define SROW   136

typedef unsigned long long u64t;

// ---------------- scratch ----------------
__device__ __half g_S[(size_t)NBG * NN];                      // 64 MB

__device__ __forceinline__ uint32_t smem_u32(const void* p) {
    uint32_t a;
    asm("{ .reg .u64 t; cvta.to.shared.u64 t, %1; cvt.u32.u64 %0, t; }" : "=r"(a) : "l"(p));
    return a;
}

// ---------------- packed f32x2 helpers ----------------
__device__ __forceinline__ u64t pack2(float a, float b) {
    u64t r; asm("mov.b64 %0, {%1, %2};" : "=l"(r) : "f"(a), "f"(b)); return r;
}
__device__ __forceinline__ void unpack2(u64t p, float& a, float& b) {
    asm("mov.b64 {%0, %1}, %2;" : "=f"(a), "=f"(b) : "l"(p));
}
__device__ __forceinline__ u64t mul2(u64t a, u64t b) {
    u64t d; asm("mul.rn.f32x2 %0, %1, %2;" : "=l"(d) : "l"(a), "l"(b)); return d;
}
__device__ __forceinline__ u64t fma2(u64t a, u64t b, u64t c) {
    u64t d; asm("fma.rn.f32x2 %0, %1, %2, %3;" : "=l"(d) : "l"(a), "l"(b), "l"(c)); return d;
}

// ---------------------------------------------------------------------------
// Kernel 1: fused split + mma.sync bf16 GEMM (3-term bf16 split, K=192 eff.)
// ---------------------------------------------------------------------------
#define SM_BYTES (2 * 128 * SROW * 2)    // 69632

__global__ __launch_bounds__(256)
void qk_gemm_mma(const float* __restrict__ q, const float* __restrict__ k)
{
    extern __shared__ __align__(16) char smem[];
    __nv_bfloat16* As = (__nv_bfloat16*)smem;          // [128][SROW]
    __nv_bfloat16* Bs = As + 128 * SROW;

    const int tid  = threadIdx.x;
    const int lane = tid & 31;
    const int w    = tid >> 5;
    const int wm   = (w & 1) * 64;
    const int wn   = (w >> 1) * 32;

    const int bg = blockIdx.z;
    const int qt = blockIdx.y * 128;
    const int kt = blockIdx.x * 128;

    const float* Qg = q + ((size_t)bg * N_TOK + qt) * DH;
    const float* Kg = k + ((size_t)bg * N_TOK + kt) * DH;

#pragma unroll
    for (int it = 0; it < 8; it++) {
        int idx = it * 256 + tid;
        int row = idx >> 4;
        int c4  = (idx & 15) * 4;
        float4 qv = *(const float4*)(Qg + (size_t)row * DH + c4);
        float4 kv = *(const float4*)(Kg + (size_t)row * DH + c4);

        __nv_bfloat16 qh0 = __float2bfloat16(qv.x), qh1 = __float2bfloat16(qv.y);
        __nv_bfloat16 qh2 = __float2bfloat16(qv.z), qh3 = __float2bfloat16(qv.w);
        __nv_bfloat16 ql0 = __float2bfloat16(qv.x - __bfloat162float(qh0));
        __nv_bfloat16 ql1 = __float2bfloat16(qv.y - __bfloat162float(qh1));
        __nv_bfloat16 ql2 = __float2bfloat16(qv.z - __bfloat162float(qh2));
        __nv_bfloat16 ql3 = __float2bfloat16(qv.w - __bfloat162float(qh3));
        __nv_bfloat16 kh0 = __float2bfloat16(kv.x), kh1 = __float2bfloat16(kv.y);
        __nv_bfloat16 kh2 = __float2bfloat16(kv.z), kh3 = __float2bfloat16(kv.w);
        __nv_bfloat16 kl0 = __float2bfloat16(kv.x - __bfloat162float(kh0));
        __nv_bfloat16 kl1 = __float2bfloat16(kv.y - __bfloat162float(kh1));
        __nv_bfloat16 kl2 = __float2bfloat16(kv.z - __bfloat162float(kh2));
        __nv_bfloat16 kl3 = __float2bfloat16(kv.w - __bfloat162float(kh3));

        __nv_bfloat16* ap = As + row * SROW + c4;
        __nv_bfloat16* bp = Bs + row * SROW + c4;
        ap[0] = qh0; ap[1] = qh1; ap[2] = qh2; ap[3] = qh3;
        ap[64] = ql0; ap[65] = ql1; ap[66] = ql2; ap[67] = ql3;
        bp[0] = kh0; bp[1] = kh1; bp[2] = kh2; bp[3] = kh3;
        bp[64] = kl0; bp[65] = kl1; bp[66] = kl2; bp[67] = kl3;
    }
    __syncthreads();

    const uint32_t a_base = smem_u32(As);
    const uint32_t b_base = smem_u32(Bs);

    const int arow  = lane & 15;
    const int akoff = (lane >> 4) * 8;
    const int brow  = (lane & 7) + ((lane >> 4) << 3);
    const int bkoff = ((lane >> 3) & 1) * 8;

    float acc[4][4][4];
#pragma unroll
    for (int mi = 0; mi < 4; mi++)
#pragma unroll
        for (int ni = 0; ni < 4; ni++)
#pragma unroll
            for (int r = 0; r < 4; r++) acc[mi][ni][r] = 0.0f;

#pragma unroll
    for (int s = 0; s < KSTEPS; s++) {
        const int ka = (s < 4) ? s * 16 : (s < 8) ? (s - 4) * 16 : 64 + (s - 8) * 16;
        const int kb = (s < 4) ? s * 16 : (s < 8) ? 64 + (s - 4) * 16 : (s - 8) * 16;

        uint32_t af[4][4], bf[4][2];
#pragma unroll
        for (int mi = 0; mi < 4; mi++) {
            uint32_t addr = a_base + (uint32_t)(((wm + mi * 16 + arow) * SROW + ka + akoff) * 2);
            asm volatile("ldmatrix.sync.aligned.m8n8.x4.shared.b16 {%0,%1,%2,%3}, [%4];"
                         : "=r"(af[mi][0]), "=r"(af[mi][1]), "=r"(af[mi][2]), "=r"(af[mi][3])
                         : "r"(addr));
        }
#pragma unroll
        for (int nip = 0; nip < 2; nip++) {
            uint32_t addr = b_base + (uint32_t)(((wn + nip * 16 + brow) * SROW + kb + bkoff) * 2);
            asm volatile("ldmatrix.sync.aligned.m8n8.x4.shared.b16 {%0,%1,%2,%3}, [%4];"
                         : "=r"(bf[2 * nip][0]), "=r"(bf[2 * nip][1]),
                           "=r"(bf[2 * nip + 1][0]), "=r"(bf[2 * nip + 1][1])
                         : "r"(addr));
        }
#pragma unroll
        for (int mi = 0; mi < 4; mi++)
#pragma unroll
            for (int ni = 0; ni < 4; ni++) {
                asm volatile(
                    "mma.sync.aligned.m16n8k16.row.col.f32.bf16.bf16.f32 "
                    "{%0,%1,%2,%3}, {%4,%5,%6,%7}, {%8,%9}, {%0,%1,%2,%3};"
                    : "+f"(acc[mi][ni][0]), "+f"(acc[mi][ni][1]),
                      "+f"(acc[mi][ni][2]), "+f"(acc[mi][ni][3])
                    : "r"(af[mi][0]), "r"(af[mi][1]), "r"(af[mi][2]), "r"(af[mi][3]),
                      "r"(bf[ni][0]), "r"(bf[ni][1]));
            }
    }

    __half* __restrict__ Sp = g_S + (size_t)bg * NN;
#pragma unroll
    for (int mi = 0; mi < 4; mi++) {
#pragma unroll
        for (int ni = 0; ni < 4; ni++) {
            int m = qt + wm + mi * 16 + (lane >> 2);
            int n = kt + wn + ni * 8 + (lane & 3) * 2;
            *(__half2*)(Sp + (size_t)m * N_TOK + n) =
                __floats2half2_rn(acc[mi][ni][0], acc[mi][ni][1]);
            *(__half2*)(Sp + (size_t)(m + 8) * N_TOK + n) =
                __floats2half2_rn(acc[mi][ni][2], acc[mi][ni][3]);
        }
    }
}

// ---------------------------------------------------------------------------
// Kernel 2: epilogue, 2 consecutive i per thread.
// LSU reduction: S loads as half2 (both i), output stores as STG.64 pairing
// the two i values of each (b,h) plane.
// ---------------------------------------------------------------------------
__global__ __launch_bounds__(128, 3)
void epilogue_kernel(const float* __restrict__ masks,
                     const float* __restrict__ proj,   // [4][32]
                     const float* __restrict__ hw,     // [8][8]
                     const float* __restrict__ hb,     // [8]
                     float* __restrict__ out)
{
    __shared__ u64t sP2[64];
    __shared__ u64t sWt2[32];
    __shared__ u64t sB2[4];

    const int tid = threadIdx.x;
    if (tid < 64) {
        int l = tid >> 4, xp = tid & 15;
        sP2[tid] = pack2(proj[l * 32 + 2 * xp], proj[l * 32 + 2 * xp + 1]);
    }
    if (tid < 32) {
        int hh = tid >> 2, hp = tid & 3;
        sWt2[tid] = pack2(hw[(2 * hp) * 8 + hh], hw[(2 * hp + 1) * 8 + hh]);
    }
    if (tid < 4) sB2[tid] = pack2(hb[2 * tid], hb[2 * tid + 1]);
    __syncthreads();

    const size_t i0 = 2 * ((size_t)blockIdx.x * 128 + tid);   // this thread: i0, i0+1
    const __half* __restrict__ Sp = g_S + i0;

    // ---- 32 independent half2 S loads (covers both i), issued up front ----
    __half2 sh[NBG];
#pragma unroll
    for (int j = 0; j < NBG; j++) sh[j] = *(const __half2*)(Sp + ((size_t)j << 20));

    float4 ma = *(const float4*)(masks + 4 * i0);       // masks for i0
    float4 mb = *(const float4*)(masks + 4 * i0 + 4);   // masks for i0+1

    // mask-mix weights, packed over h-pairs, one set per sub-i
    u64t mwA[16], mwB[16];
    {
        u64t ax = pack2(ma.x, ma.x), ay = pack2(ma.y, ma.y);
        u64t az = pack2(ma.z, ma.z), aw = pack2(ma.w, ma.w);
        u64t bx = pack2(mb.x, mb.x), by = pack2(mb.y, mb.y);
        u64t bz = pack2(mb.z, mb.z), bw = pack2(mb.w, mb.w);
#pragma unroll
        for (int xp = 0; xp < 16; xp++) {
            u64t p0 = sP2[xp], p1 = sP2[16 + xp], p2 = sP2[32 + xp], p3 = sP2[48 + xp];
            u64t tA = mul2(ax, p0);
            tA = fma2(ay, p1, tA);
            tA = fma2(az, p2, tA);
            tA = fma2(aw, p3, tA);
            mwA[xp] = tA;
            u64t tB = mul2(bx, p0);
            tB = fma2(by, p1, tB);
            tB = fma2(bz, p2, tB);
            tB = fma2(bw, p3, tB);
            mwB[xp] = tB;
        }
    }

#pragma unroll
    for (int b = 0; b < NB; b++) {
        float2 f0 = __half22float2(sh[b * 4 + 0]);   // .x = i0, .y = i0+1
        float2 f1 = __half22float2(sh[b * 4 + 1]);
        float2 f2 = __half22float2(sh[b * 4 + 2]);
        float2 f3 = __half22float2(sh[b * 4 + 3]);

        u64t a0 = pack2(f0.x, f0.x), a1 = pack2(f1.x, f1.x);
        u64t a2 = pack2(f2.x, f2.x), a3 = pack2(f3.x, f3.x);
        u64t b0 = pack2(f0.y, f0.y), b1 = pack2(f1.y, f1.y);
        u64t b2 = pack2(f2.y, f2.y), b3 = pack2(f3.y, f3.y);

        // mix over g, relu -> broadcast packs per h
        u64t pvA[8], pvB[8];
#pragma unroll
        for (int hp = 0; hp < 4; hp++) {
            u64t tA = mul2(a0, mwA[hp]);
            tA = fma2(a1, mwA[4 + hp], tA);
            tA = fma2(a2, mwA[8 + hp], tA);
            tA = fma2(a3, mwA[12 + hp], tA);
            float vA0, vA1; unpack2(tA, vA0, vA1);
            vA0 = fmaxf(vA0, 0.0f); vA1 = fmaxf(vA1, 0.0f);
            pvA[2 * hp]     = pack2(vA0, vA0);
            pvA[2 * hp + 1] = pack2(vA1, vA1);

            u64t tB = mul2(b0, mwB[hp]);
            tB = fma2(b1, mwB[4 + hp], tB);
            tB = fma2(b2, mwB[8 + hp], tB);
            tB = fma2(b3, mwB[12 + hp], tB);
            float vB0, vB1; unpack2(tB, vB0, vB1);
            vB0 = fmaxf(vB0, 0.0f); vB1 = fmaxf(vB1, 0.0f);
            pvB[2 * hp]     = pack2(vB0, vB0);
            pvB[2 * hp + 1] = pack2(vB1, vB1);
        }

        // head projection; store float2 {i0, i0+1} per (b,h) plane
#pragma unroll
        for (int hp = 0; hp < 4; hp++) {
            u64t oA = sB2[hp], oB = sB2[hp];
#pragma unroll
            for (int hh = 0; hh < 8; hh++) {
                u64t wv = sWt2[hh * 4 + hp];
                oA = fma2(pvA[hh], wv, oA);
                oB = fma2(pvB[hh], wv, oB);
            }
            float oA0, oA1, oB0, oB1;
            unpack2(oA, oA0, oA1);    // i0: h=2hp, 2hp+1
            unpack2(oB, oB0, oB1);    // i0+1
            *(float2*)(out + ((size_t)(b * 8 + 2 * hp)     << 20) + i0) = make_float2(oA0, oB0);
            *(float2*)(out + ((size_t)(b * 8 + 2 * hp + 1) << 20) + i0) = make_float2(oA1, oB1);
        }
    }
}

extern "C" void kernel_launch(void* const* d_in, const int* in_sizes, int n_in,
                              void* d_out, int out_size)
{
    const float* q     = (const float*)d_in[0];
    const float* k     = (const float*)d_in[1];
    const float* masks = (const float*)d_in[2];
    const float* proj  = (const float*)d_in[3];
    const float* hw    = (const float*)d_in[4];
    const float* hb    = (const float*)d_in[5];
    float* out = (float*)d_out;

    cudaFuncSetAttribute(qk_gemm_mma, cudaFuncAttributeMaxDynamicSharedMemorySize, SM_BYTES);

    dim3 g1(N_TOK / 128, N_TOK / 128, NBG);
    qk_gemm_mma<<<g1, 256, SM_BYTES>>>(q, k);

    epilogue_kernel<<<NN / 256, 128>>>(masks, proj, hw, hb, out);
}